// round 10
// baseline (speedup 1.0000x reference)
#include <cuda_runtime.h>
#include <cuda_bf16.h>
#include <cstdint>
#include <math.h>

// Problem constants
#define BB 8
#define TT 1024
#define EE 768
#define HH 12
#define DD 64
#define MM (BB*TT)        // 8192
#define E3 (3*EE)         // 2304

// Scratch (allocation-free rule: __device__ globals)
__device__ float g_qkv[(size_t)MM * E3];    // 75.5 MB (tf32-rounded)
__device__ float g_attn[(size_t)MM * EE];   // 25 MB   (tf32-rounded)
__device__ float g_x_tf[(size_t)MM * EE];   // 25 MB
__device__ float g_wa_tf[(size_t)EE * E3];  // 7.1 MB
__device__ float g_wp_tf[(size_t)EE * EE];  // 2.4 MB

__device__ __forceinline__ uint32_t f2tf(float x) {
    uint32_t r;
    asm("cvt.rna.tf32.f32 %0, %1;" : "=r"(r) : "f"(x));
    return r;
}

__device__ __forceinline__ void cp16(void* smem_ptr, const void* gmem_ptr) {
    uint32_t s = (uint32_t)__cvta_generic_to_shared(smem_ptr);
    asm volatile("cp.async.cg.shared.global [%0], [%1], 16;\n"
                 :: "r"(s), "l"(gmem_ptr));
}
#define CP_COMMIT asm volatile("cp.async.commit_group;\n" ::: "memory")
#define CP_WAIT0  asm volatile("cp.async.wait_group 0;\n" ::: "memory")

__device__ __forceinline__ void mma_tf32(float c[4], const uint32_t a[4],
                                         uint32_t b0, uint32_t b1) {
    asm volatile(
        "mma.sync.aligned.m16n8k8.row.col.f32.tf32.tf32.f32 "
        "{%0,%1,%2,%3}, {%4,%5,%6,%7}, {%8,%9}, {%0,%1,%2,%3};\n"
        : "+f"(c[0]), "+f"(c[1]), "+f"(c[2]), "+f"(c[3])
        : "r"(a[0]), "r"(a[1]), "r"(a[2]), "r"(a[3]), "r"(b0), "r"(b1));
}

// ---------------------------------------------------------------------------
// Merged tf32 pre-round for x, w_attn, w_proj (one launch)
// ---------------------------------------------------------------------------
#define N4_X  ((MM * EE) / 4)
#define N4_WA ((EE * E3) / 4)
#define N4_WP ((EE * EE) / 4)
__global__ __launch_bounds__(256) void cvt3_tf32_kernel(
    const float* __restrict__ x,  float* __restrict__ xo,
    const float* __restrict__ wa, float* __restrict__ wao,
    const float* __restrict__ wp, float* __restrict__ wpo)
{
    const int total = N4_X + N4_WA + N4_WP;
    int i = blockIdx.x * 256 + threadIdx.x;
    int stride = gridDim.x * 256;
    for (; i < total; i += stride) {
        const float4* src;
        float4* dst;
        int j = i;
        if (j < N4_X)            { src = (const float4*)x  + j; dst = (float4*)xo  + j; }
        else if ((j -= N4_X) < N4_WA) { src = (const float4*)wa + j; dst = (float4*)wao + j; }
        else { j -= N4_WA;         src = (const float4*)wp + j; dst = (float4*)wpo + j; }
        float4 v = *src;
        v.x = __uint_as_float(f2tf(v.x));
        v.y = __uint_as_float(f2tf(v.y));
        v.z = __uint_as_float(f2tf(v.z));
        v.w = __uint_as_float(f2tf(v.w));
        *dst = v;
    }
}

// ---------------------------------------------------------------------------
// Persistent GEMM, single-barrier pipeline:
//   per k-tile: wait_group 0 -> ONE syncthreads -> issue next DMA -> compute
// The single barrier provides both cross-thread visibility of the landed
// stage and overwrite-safety for the buffer consumed last iteration.
// 128x128 CTA tile, 4 warps (64x64), K-step 32, 2-stage, 3 CTAs/SM.
// ---------------------------------------------------------------------------
#define GA_STRIDE 36
#define GW_STRIDE 136
#define GA_WORDS (128 * GA_STRIDE)
#define GW_WORDS (32 * GW_STRIDE)
#define STG_WORDS (GA_WORDS + GW_WORDS)
#define GEMM_SMEM (2 * STG_WORDS * 4)
#define GK 768
#define GNK 24

template<int NX, int ROUND_OUT>
__global__ __launch_bounds__(128, 3) void gemm_bias_kernel(
    const float* __restrict__ A, const float* __restrict__ W,
    const float* __restrict__ bias, float* __restrict__ C)
{
    extern __shared__ float smem[];
    constexpr int NN = NX * 128;
    constexpr int NTILES = NX * (MM / 128);

    const int tid  = threadIdx.x;
    const int warp = tid >> 5, lane = tid & 31;
    const int wm   = (warp >> 1) * 64;
    const int wn   = (warp & 1) * 64;
    const int lr   = lane >> 2, lc = lane & 3;
    const int G    = gridDim.x;

    auto load_stage = [&](int s, int m0, int n0, int kk) {
        float* As = smem + s * STG_WORDS;
        float* Ws = As + GA_WORDS;
#pragma unroll
        for (int i = 0; i < 8; i++) {
            int idx = i * 128 + tid;
            int r = idx >> 3, c = (idx & 7) << 2;
            cp16(&As[r * GA_STRIDE + c], &A[(size_t)(m0 + r) * GK + kk + c]);
        }
#pragma unroll
        for (int i = 0; i < 8; i++) {
            int idx = i * 128 + tid;
            int r = idx >> 5, c = (idx & 31) << 2;
            cp16(&Ws[r * GW_STRIDE + c], &W[(size_t)(kk + r) * NN + n0 + c]);
        }
    };

    // Prologue: first tile's stage 0
    {
        int t0 = blockIdx.x;
        if (t0 < NTILES)
            load_stage(0, (t0 / NX) * 128, (t0 % NX) * 128, 0);
        CP_COMMIT;
    }

    for (int t = blockIdx.x; t < NTILES; t += G) {
        const int m0 = (t / NX) * 128;
        const int n0 = (t % NX) * 128;
        const int tn = t + G;

        float acc[4][8][4];
#pragma unroll
        for (int i = 0; i < 4; i++)
#pragma unroll
            for (int j = 0; j < 8; j++)
#pragma unroll
                for (int k = 0; k < 4; k++) acc[i][j][k] = 0.f;

        for (int kt = 0; kt < GNK; kt++) {
            const int s = kt & 1;
            CP_WAIT0;            // this thread's copies for stage s landed
            __syncthreads();     // all copies visible; all warps past stage s^1
            if (kt + 1 < GNK) {
                load_stage(s ^ 1, m0, n0, (kt + 1) << 5);
            } else if (tn < NTILES) {
                load_stage(s ^ 1, (tn / NX) * 128, (tn % NX) * 128, 0);
            }
            CP_COMMIT;

            const float* As = smem + s * STG_WORDS;
            const float* Ws = As + GA_WORDS;
#pragma unroll
            for (int ks = 0; ks < 4; ks++) {
                const int kb = ks * 8;
                uint32_t a[4][4];
#pragma unroll
                for (int mt = 0; mt < 4; mt++) {
                    int mr = wm + mt * 16;
                    a[mt][0] = __float_as_uint(As[(mr + lr) * GA_STRIDE + kb + lc]);
                    a[mt][1] = __float_as_uint(As[(mr + lr + 8) * GA_STRIDE + kb + lc]);
                    a[mt][2] = __float_as_uint(As[(mr + lr) * GA_STRIDE + kb + lc + 4]);
                    a[mt][3] = __float_as_uint(As[(mr + lr + 8) * GA_STRIDE + kb + lc + 4]);
                }
#pragma unroll
                for (int half = 0; half < 2; half++) {
                    uint32_t b[4][2];
#pragma unroll
                    for (int j = 0; j < 4; j++) {
                        int nc = wn + (half * 4 + j) * 8;
                        b[j][0] = __float_as_uint(Ws[(kb + lc) * GW_STRIDE + nc + lr]);
                        b[j][1] = __float_as_uint(Ws[(kb + lc + 4) * GW_STRIDE + nc + lr]);
                    }
#pragma unroll
                    for (int mt = 0; mt < 4; mt++)
#pragma unroll
                        for (int j = 0; j < 4; j++)
                            mma_tf32(acc[mt][half * 4 + j], a[mt], b[j][0], b[j][1]);
                }
            }
        }

        // Epilogue (overlaps next tile's in-flight stage-0 DMA)
#pragma unroll
        for (int mt = 0; mt < 4; mt++) {
#pragma unroll
            for (int nt = 0; nt < 8; nt++) {
                int row = m0 + wm + mt * 16 + lr;
                int col = n0 + wn + nt * 8 + 2 * lc;
                float b0 = __ldg(&bias[col]), b1 = __ldg(&bias[col + 1]);
                float v0 = acc[mt][nt][0] + b0;
                float v1 = acc[mt][nt][1] + b1;
                float v2 = acc[mt][nt][2] + b0;
                float v3 = acc[mt][nt][3] + b1;
                if (ROUND_OUT) {
                    v0 = __uint_as_float(f2tf(v0));
                    v1 = __uint_as_float(f2tf(v1));
                    v2 = __uint_as_float(f2tf(v2));
                    v3 = __uint_as_float(f2tf(v3));
                }
                C[(size_t)row * NN + col]           = v0;
                C[(size_t)row * NN + col + 1]       = v1;
                C[(size_t)(row + 8) * NN + col]     = v2;
                C[(size_t)(row + 8) * NN + col + 1] = v3;
            }
        }
        // NOTE: no barrier needed here; the first k-tile of the next tile
        // starts with CP_WAIT0 + syncthreads which re-establishes safety.
    }
}

// ---------------------------------------------------------------------------
// Flash attention, causal (R7 structure), single-barrier pipeline:
//   per iter: wait_group 0 -> ONE syncthreads -> issue next K/V DMA -> compute
// 64 q-rows/block, 4 warps, Bc=64, Q frags hoisted, P in dead Q region.
// ---------------------------------------------------------------------------
#define FQ_STRIDE 68
#define FV_STRIDE 72
#define FQ_WORDS (64 * FQ_STRIDE)
#define FV_WORDS (64 * FV_STRIDE)
#define FLASH_SMEM ((FQ_WORDS + 2 * FQ_WORDS + 2 * FV_WORDS) * 4)

__global__ __launch_bounds__(128) void flash_attn_kernel(
    const float* __restrict__ qkv, float* __restrict__ attn_out)
{
    extern __shared__ uint32_t sm[];
    uint32_t* QP   = sm;                                  // Q (prologue) then P
    float*    Kraw = (float*)(sm + FQ_WORDS);             // 2 stages [64][68]
    float*    Vraw = (float*)(sm + FQ_WORDS + 2 * FQ_WORDS);

    const int b = blockIdx.z, h = blockIdx.y, qt = blockIdx.x;
    const int tid = threadIdx.x, warp = tid >> 5, lane = tid & 31;
    const int lr = lane >> 2, lc = lane & 3;

    const float* base = qkv + (size_t)b * TT * E3;
    const int qoff = h * DD, koff = EE + h * DD, voff = 2 * EE + h * DD;
    const int qrow0 = qt * 64;

    auto load_kv = [&](int s, int kt) {
        float* Kd = Kraw + s * FQ_WORDS;
        float* Vd = Vraw + s * FV_WORDS;
#pragma unroll
        for (int i = 0; i < 8; i++) {
            int idx = i * 128 + tid;
            int r = idx >> 4, c = (idx & 15) << 2;
            size_t row = (size_t)(kt * 64 + r) * E3;
            cp16(&Kd[r * FQ_STRIDE + c], &base[row + koff + c]);
            cp16(&Vd[r * FV_STRIDE + c], &base[row + voff + c]);
        }
    };

    load_kv(0, 0); CP_COMMIT;

#pragma unroll
    for (int i = 0; i < 8; i++) {
        int idx = i * 128 + tid;
        int r = idx >> 4, c = (idx & 15) << 2;
        float4 v = *(const float4*)&base[(size_t)(qrow0 + r) * E3 + qoff + c];
        QP[r * FQ_STRIDE + c]     = __float_as_uint(v.x * 0.125f);
        QP[r * FQ_STRIDE + c + 1] = __float_as_uint(v.y * 0.125f);
        QP[r * FQ_STRIDE + c + 2] = __float_as_uint(v.z * 0.125f);
        QP[r * FQ_STRIDE + c + 3] = __float_as_uint(v.w * 0.125f);
    }
    __syncthreads();                     // Q visible to all warps

    uint32_t aq[8][4];                   // loop-invariant Q fragments (own rows)
#pragma unroll
    for (int ks = 0; ks < 8; ks++) {
        aq[ks][0] = QP[(warp * 16 + lr) * FQ_STRIDE + ks * 8 + lc];
        aq[ks][1] = QP[(warp * 16 + lr + 8) * FQ_STRIDE + ks * 8 + lc];
        aq[ks][2] = QP[(warp * 16 + lr) * FQ_STRIDE + ks * 8 + lc + 4];
        aq[ks][3] = QP[(warp * 16 + lr + 8) * FQ_STRIDE + ks * 8 + lc + 4];
    }

    float o[8][4];
#pragma unroll
    for (int i = 0; i < 8; i++)
#pragma unroll
        for (int j = 0; j < 4; j++) o[i][j] = 0.f;
    float m0r = -1e30f, m1r = -1e30f, l0 = 0.f, l1 = 0.f;

    for (int kt = 0; kt <= qt; kt++) {
        const int s = kt & 1;
        CP_WAIT0;                        // this thread's K/V copies landed
        __syncthreads();                 // visible to all; all warps past s^1
        if (kt < qt) load_kv(s ^ 1, kt + 1);
        CP_COMMIT;

        const float* Kf = Kraw + s * FQ_WORDS;
        const float* Vf = Vraw + s * FV_WORDS;

        float sv[8][4];
#pragma unroll
        for (int i = 0; i < 8; i++)
#pragma unroll
            for (int j = 0; j < 4; j++) sv[i][j] = 0.f;

#pragma unroll
        for (int nt = 0; nt < 8; nt++) {
#pragma unroll
            for (int ks = 0; ks < 8; ks++) {
                uint32_t b0 = __float_as_uint(Kf[(nt * 8 + lr) * FQ_STRIDE + ks * 8 + lc]);
                uint32_t b1 = __float_as_uint(Kf[(nt * 8 + lr) * FQ_STRIDE + ks * 8 + lc + 4]);
                mma_tf32(sv[nt], aq[ks], b0, b1);
            }
        }

        const int q0 = warp * 16 + lr, q1 = q0 + 8;
        if (kt == qt) {
#pragma unroll
            for (int nt = 0; nt < 8; nt++) {
                int c0 = nt * 8 + 2 * lc;
                if (c0     > q0) sv[nt][0] = -1e30f;
                if (c0 + 1 > q0) sv[nt][1] = -1e30f;
                if (c0     > q1) sv[nt][2] = -1e30f;
                if (c0 + 1 > q1) sv[nt][3] = -1e30f;
            }
        }

        float t0 = -1e30f, t1 = -1e30f;
#pragma unroll
        for (int nt = 0; nt < 8; nt++) {
            t0 = fmaxf(t0, fmaxf(sv[nt][0], sv[nt][1]));
            t1 = fmaxf(t1, fmaxf(sv[nt][2], sv[nt][3]));
        }
        t0 = fmaxf(t0, __shfl_xor_sync(0xffffffff, t0, 1));
        t0 = fmaxf(t0, __shfl_xor_sync(0xffffffff, t0, 2));
        t1 = fmaxf(t1, __shfl_xor_sync(0xffffffff, t1, 1));
        t1 = fmaxf(t1, __shfl_xor_sync(0xffffffff, t1, 2));

        float mn0 = fmaxf(m0r, t0), mn1 = fmaxf(m1r, t1);
        float al0 = __expf(m0r - mn0), al1 = __expf(m1r - mn1);
        m0r = mn0; m1r = mn1;

        float sum0 = 0.f, sum1 = 0.f;
#pragma unroll
        for (int nt = 0; nt < 8; nt++) {
            sv[nt][0] = __expf(sv[nt][0] - mn0);
            sv[nt][1] = __expf(sv[nt][1] - mn0);
            sv[nt][2] = __expf(sv[nt][2] - mn1);
            sv[nt][3] = __expf(sv[nt][3] - mn1);
            sum0 += sv[nt][0] + sv[nt][1];
            sum1 += sv[nt][2] + sv[nt][3];
        }
        sum0 += __shfl_xor_sync(0xffffffff, sum0, 1);
        sum0 += __shfl_xor_sync(0xffffffff, sum0, 2);
        sum1 += __shfl_xor_sync(0xffffffff, sum1, 1);
        sum1 += __shfl_xor_sync(0xffffffff, sum1, 2);
        l0 = l0 * al0 + sum0;
        l1 = l1 * al1 + sum1;

#pragma unroll
        for (int nt = 0; nt < 8; nt++) {
            o[nt][0] *= al0; o[nt][1] *= al0;
            o[nt][2] *= al1; o[nt][3] *= al1;
        }

#pragma unroll
        for (int nt = 0; nt < 8; nt++) {
            int c0 = nt * 8 + 2 * lc;
            QP[(warp * 16 + lr) * FQ_STRIDE + c0]         = f2tf(sv[nt][0]);
            QP[(warp * 16 + lr) * FQ_STRIDE + c0 + 1]     = f2tf(sv[nt][1]);
            QP[(warp * 16 + lr + 8) * FQ_STRIDE + c0]     = f2tf(sv[nt][2]);
            QP[(warp * 16 + lr + 8) * FQ_STRIDE + c0 + 1] = f2tf(sv[nt][3]);
        }
        __syncwarp();

#pragma unroll
        for (int ks = 0; ks < 8; ks++) {
            uint32_t ap[4];
            ap[0] = QP[(warp * 16 + lr) * FQ_STRIDE + ks * 8 + lc];
            ap[1] = QP[(warp * 16 + lr + 8) * FQ_STRIDE + ks * 8 + lc];
            ap[2] = QP[(warp * 16 + lr) * FQ_STRIDE + ks * 8 + lc + 4];
            ap[3] = QP[(warp * 16 + lr + 8) * FQ_STRIDE + ks * 8 + lc + 4];
#pragma unroll
            for (int nt = 0; nt < 8; nt++) {
                uint32_t b0 = __float_as_uint(Vf[(ks * 8 + lc) * FV_STRIDE + nt * 8 + lr]);
                uint32_t b1 = __float_as_uint(Vf[(ks * 8 + lc + 4) * FV_STRIDE + nt * 8 + lr]);
                mma_tf32(o[nt], ap, b0, b1);
            }
        }
    }

    const float inv0 = 1.f / l0, inv1 = 1.f / l1;
    const size_t row0 = (size_t)(b * TT + qrow0 + warp * 16 + lr) * EE + h * DD;
#pragma unroll
    for (int nt = 0; nt < 8; nt++) {
        int c = nt * 8 + 2 * lc;
        attn_out[row0 + c]              = __uint_as_float(f2tf(o[nt][0] * inv0));
        attn_out[row0 + c + 1]          = __uint_as_float(f2tf(o[nt][1] * inv0));
        attn_out[row0 + 8 * EE + c]     = __uint_as_float(f2tf(o[nt][2] * inv1));
        attn_out[row0 + 8 * EE + c + 1] = __uint_as_float(f2tf(o[nt][3] * inv1));
    }
}

// ---------------------------------------------------------------------------
extern "C" void kernel_launch(void* const* d_in, const int* in_sizes, int n_in,
                              void* d_out, int out_size)
{
    const float* x      = (const float*)d_in[0];
    const float* w_attn = (const float*)d_in[1];
    const float* b_attn = (const float*)d_in[2];
    const float* w_proj = (const float*)d_in[3];
    const float* b_proj = (const float*)d_in[4];
    float* out = (float*)d_out;

    float *qkv_ptr, *attn_ptr, *xtf, *watf, *wptf;
    cudaGetSymbolAddress((void**)&qkv_ptr, g_qkv);
    cudaGetSymbolAddress((void**)&attn_ptr, g_attn);
    cudaGetSymbolAddress((void**)&xtf,  g_x_tf);
    cudaGetSymbolAddress((void**)&watf, g_wa_tf);
    cudaGetSymbolAddress((void**)&wptf, g_wp_tf);

    cudaFuncSetAttribute(gemm_bias_kernel<18, 1>,
                         cudaFuncAttributeMaxDynamicSharedMemorySize, GEMM_SMEM);
    cudaFuncSetAttribute(gemm_bias_kernel<6, 0>,
                         cudaFuncAttributeMaxDynamicSharedMemorySize, GEMM_SMEM);
    cudaFuncSetAttribute(flash_attn_kernel,
                         cudaFuncAttributeMaxDynamicSharedMemorySize, FLASH_SMEM);

    // 0) pre-round inputs to the tf32 grid (single launch)
    cvt3_tf32_kernel<<<888, 256>>>(x, xtf, w_attn, watf, w_proj, wptf);

    // 1) QKV = x @ w_attn + b_attn [8192, 2304], persistent 444-CTA grid
    gemm_bias_kernel<18, 1><<<444, 128, GEMM_SMEM>>>(xtf, watf, b_attn, qkv_ptr);

    // 2) causal flash attention (Br=64) -> g_attn
    flash_attn_kernel<<<dim3(TT / 64, HH, BB), 128, FLASH_SMEM>>>(qkv_ptr, attn_ptr);

    // 3) out = attn @ w_proj + b_proj [8192, 768] (single wave)
    gemm_bias_kernel<6, 0><<<384, 128, GEMM_SMEM>>>(attn_ptr, wptf, b_proj, out);
}

// round 11
// speedup vs baseline: 1.0330x; 1.0330x over previous
#include <cuda_runtime.h>
#include <cuda_bf16.h>
#include <cstdint>
#include <math.h>

// Problem constants
#define BB 8
#define TT 1024
#define EE 768
#define HH 12
#define DD 64
#define MM (BB*TT)        // 8192
#define E3 (3*EE)         // 2304

// Scratch (allocation-free rule: __device__ globals)
__device__ float g_qkv[(size_t)MM * E3];    // 75.5 MB (tf32-rounded)
__device__ float g_attn[(size_t)MM * EE];   // 25 MB   (tf32-rounded)
__device__ float g_x_tf[(size_t)MM * EE];   // 25 MB
__device__ float g_wa_tf[(size_t)EE * E3];  // 7.1 MB
__device__ float g_wp_tf[(size_t)EE * EE];  // 2.4 MB

__device__ __forceinline__ uint32_t f2tf(float x) {
    uint32_t r;
    asm("cvt.rna.tf32.f32 %0, %1;" : "=r"(r) : "f"(x));
    return r;
}

__device__ __forceinline__ void cp16(void* smem_ptr, const void* gmem_ptr) {
    uint32_t s = (uint32_t)__cvta_generic_to_shared(smem_ptr);
    asm volatile("cp.async.cg.shared.global [%0], [%1], 16;\n"
                 :: "r"(s), "l"(gmem_ptr));
}
#define CP_COMMIT asm volatile("cp.async.commit_group;\n" ::: "memory")
#define CP_WAIT0  asm volatile("cp.async.wait_group 0;\n" ::: "memory")

__device__ __forceinline__ void mma_tf32(float c[4], const uint32_t a[4],
                                         uint32_t b0, uint32_t b1) {
    asm volatile(
        "mma.sync.aligned.m16n8k8.row.col.f32.tf32.tf32.f32 "
        "{%0,%1,%2,%3}, {%4,%5,%6,%7}, {%8,%9}, {%0,%1,%2,%3};\n"
        : "+f"(c[0]), "+f"(c[1]), "+f"(c[2]), "+f"(c[3])
        : "r"(a[0]), "r"(a[1]), "r"(a[2]), "r"(a[3]), "r"(b0), "r"(b1));
}

// ---------------------------------------------------------------------------
// Merged tf32 pre-round for x, w_attn, w_proj (one launch)
// ---------------------------------------------------------------------------
#define N4_X  ((MM * EE) / 4)
#define N4_WA ((EE * E3) / 4)
#define N4_WP ((EE * EE) / 4)
__global__ __launch_bounds__(256) void cvt3_tf32_kernel(
    const float* __restrict__ x,  float* __restrict__ xo,
    const float* __restrict__ wa, float* __restrict__ wao,
    const float* __restrict__ wp, float* __restrict__ wpo)
{
    const int total = N4_X + N4_WA + N4_WP;
    int i = blockIdx.x * 256 + threadIdx.x;
    int stride = gridDim.x * 256;
    for (; i < total; i += stride) {
        const float4* src;
        float4* dst;
        int j = i;
        if (j < N4_X)            { src = (const float4*)x  + j; dst = (float4*)xo  + j; }
        else if ((j -= N4_X) < N4_WA) { src = (const float4*)wa + j; dst = (float4*)wao + j; }
        else { j -= N4_WA;         src = (const float4*)wp + j; dst = (float4*)wpo + j; }
        float4 v = *src;
        v.x = __uint_as_float(f2tf(v.x));
        v.y = __uint_as_float(f2tf(v.y));
        v.z = __uint_as_float(f2tf(v.z));
        v.w = __uint_as_float(f2tf(v.w));
        *dst = v;
    }
}

// ---------------------------------------------------------------------------
// Persistent GEMM (R10 version, unchanged): single-barrier 2-stage pipeline,
// 128x128 CTA tile, 4 warps (64x64), K-step 32, 3 CTAs/SM.
// ---------------------------------------------------------------------------
#define GA_STRIDE 36
#define GW_STRIDE 136
#define GA_WORDS (128 * GA_STRIDE)
#define GW_WORDS (32 * GW_STRIDE)
#define STG_WORDS (GA_WORDS + GW_WORDS)
#define GEMM_SMEM (2 * STG_WORDS * 4)
#define GK 768
#define GNK 24

template<int NX, int ROUND_OUT>
__global__ __launch_bounds__(128, 3) void gemm_bias_kernel(
    const float* __restrict__ A, const float* __restrict__ W,
    const float* __restrict__ bias, float* __restrict__ C)
{
    extern __shared__ float smem[];
    constexpr int NN = NX * 128;
    constexpr int NTILES = NX * (MM / 128);

    const int tid  = threadIdx.x;
    const int warp = tid >> 5, lane = tid & 31;
    const int wm   = (warp >> 1) * 64;
    const int wn   = (warp & 1) * 64;
    const int lr   = lane >> 2, lc = lane & 3;
    const int G    = gridDim.x;

    auto load_stage = [&](int s, int m0, int n0, int kk) {
        float* As = smem + s * STG_WORDS;
        float* Ws = As + GA_WORDS;
#pragma unroll
        for (int i = 0; i < 8; i++) {
            int idx = i * 128 + tid;
            int r = idx >> 3, c = (idx & 7) << 2;
            cp16(&As[r * GA_STRIDE + c], &A[(size_t)(m0 + r) * GK + kk + c]);
        }
#pragma unroll
        for (int i = 0; i < 8; i++) {
            int idx = i * 128 + tid;
            int r = idx >> 5, c = (idx & 31) << 2;
            cp16(&Ws[r * GW_STRIDE + c], &W[(size_t)(kk + r) * NN + n0 + c]);
        }
    };

    {
        int t0 = blockIdx.x;
        if (t0 < NTILES)
            load_stage(0, (t0 / NX) * 128, (t0 % NX) * 128, 0);
        CP_COMMIT;
    }

    for (int t = blockIdx.x; t < NTILES; t += G) {
        const int m0 = (t / NX) * 128;
        const int n0 = (t % NX) * 128;
        const int tn = t + G;

        float acc[4][8][4];
#pragma unroll
        for (int i = 0; i < 4; i++)
#pragma unroll
            for (int j = 0; j < 8; j++)
#pragma unroll
                for (int k = 0; k < 4; k++) acc[i][j][k] = 0.f;

        for (int kt = 0; kt < GNK; kt++) {
            const int s = kt & 1;
            CP_WAIT0;
            __syncthreads();
            if (kt + 1 < GNK) {
                load_stage(s ^ 1, m0, n0, (kt + 1) << 5);
            } else if (tn < NTILES) {
                load_stage(s ^ 1, (tn / NX) * 128, (tn % NX) * 128, 0);
            }
            CP_COMMIT;

            const float* As = smem + s * STG_WORDS;
            const float* Ws = As + GA_WORDS;
#pragma unroll
            for (int ks = 0; ks < 4; ks++) {
                const int kb = ks * 8;
                uint32_t a[4][4];
#pragma unroll
                for (int mt = 0; mt < 4; mt++) {
                    int mr = wm + mt * 16;
                    a[mt][0] = __float_as_uint(As[(mr + lr) * GA_STRIDE + kb + lc]);
                    a[mt][1] = __float_as_uint(As[(mr + lr + 8) * GA_STRIDE + kb + lc]);
                    a[mt][2] = __float_as_uint(As[(mr + lr) * GA_STRIDE + kb + lc + 4]);
                    a[mt][3] = __float_as_uint(As[(mr + lr + 8) * GA_STRIDE + kb + lc + 4]);
                }
#pragma unroll
                for (int half = 0; half < 2; half++) {
                    uint32_t b[4][2];
#pragma unroll
                    for (int j = 0; j < 4; j++) {
                        int nc = wn + (half * 4 + j) * 8;
                        b[j][0] = __float_as_uint(Ws[(kb + lc) * GW_STRIDE + nc + lr]);
                        b[j][1] = __float_as_uint(Ws[(kb + lc + 4) * GW_STRIDE + nc + lr]);
                    }
#pragma unroll
                    for (int mt = 0; mt < 4; mt++)
#pragma unroll
                        for (int j = 0; j < 4; j++)
                            mma_tf32(acc[mt][half * 4 + j], a[mt], b[j][0], b[j][1]);
                }
            }
        }

#pragma unroll
        for (int mt = 0; mt < 4; mt++) {
#pragma unroll
            for (int nt = 0; nt < 8; nt++) {
                int row = m0 + wm + mt * 16 + lr;
                int col = n0 + wn + nt * 8 + 2 * lc;
                float b0 = __ldg(&bias[col]), b1 = __ldg(&bias[col + 1]);
                float v0 = acc[mt][nt][0] + b0;
                float v1 = acc[mt][nt][1] + b1;
                float v2 = acc[mt][nt][2] + b0;
                float v3 = acc[mt][nt][3] + b1;
                if (ROUND_OUT) {
                    v0 = __uint_as_float(f2tf(v0));
                    v1 = __uint_as_float(f2tf(v1));
                    v2 = __uint_as_float(f2tf(v2));
                    v3 = __uint_as_float(f2tf(v3));
                }
                C[(size_t)row * NN + col]           = v0;
                C[(size_t)row * NN + col + 1]       = v1;
                C[(size_t)(row + 8) * NN + col]     = v2;
                C[(size_t)(row + 8) * NN + col + 1] = v3;
            }
        }
    }
}

// ---------------------------------------------------------------------------
// Flash attention v4, causal. 64 q-rows/block, 4 warps, Bc=64.
// - P never touches smem: S-accum (c-frag) -> PV A-operand (a-frag) via
//   intra-quad shfl.idx permutation (srcLane = (lane&28)|(lc>>1), +2).
// - No Q/P smem region: Q stages through K stage-1 buffer (cp.async), aq
//   fragments scaled x0.125 in registers. Smem 70 KB -> 3 CTAs/SM.
// ---------------------------------------------------------------------------
#define FQ_STRIDE 68
#define FV_STRIDE 72
#define FK_WORDS (64 * FQ_STRIDE)
#define FV_WORDS (64 * FV_STRIDE)
#define FLASH_SMEM ((2 * FK_WORDS + 2 * FV_WORDS) * 4)   // 71680 B

__global__ __launch_bounds__(128, 3) void flash_attn_kernel(
    const float* __restrict__ qkv, float* __restrict__ attn_out)
{
    extern __shared__ uint32_t sm[];
    float* Kraw = (float*)sm;                       // 2 stages [64][68]
    float* Vraw = (float*)(sm + 2 * FK_WORDS);      // 2 stages [64][72]

    const int b = blockIdx.z, h = blockIdx.y, qt = blockIdx.x;
    const int tid = threadIdx.x, warp = tid >> 5, lane = tid & 31;
    const int lr = lane >> 2, lc = lane & 3;

    const float* base = qkv + (size_t)b * TT * E3;
    const int qoff = h * DD, koff = EE + h * DD, voff = 2 * EE + h * DD;
    const int qrow0 = qt * 64;

    auto load_kv = [&](int s, int kt) {
        float* Kd = Kraw + s * FK_WORDS;
        float* Vd = Vraw + s * FV_WORDS;
#pragma unroll
        for (int i = 0; i < 8; i++) {
            int idx = i * 128 + tid;
            int r = idx >> 4, c = (idx & 15) << 2;
            size_t row = (size_t)(kt * 64 + r) * E3;
            cp16(&Kd[r * FQ_STRIDE + c], &base[row + koff + c]);
            cp16(&Vd[r * FV_STRIDE + c], &base[row + voff + c]);
        }
    };

    // Prologue: Q -> K stage-1 buffer (DMA), K0/V0 -> stage 0 (DMA).
    {
        float* Qtmp = Kraw + FK_WORDS;
#pragma unroll
        for (int i = 0; i < 8; i++) {
            int idx = i * 128 + tid;
            int r = idx >> 4, c = (idx & 15) << 2;
            cp16(&Qtmp[r * FQ_STRIDE + c],
                 &base[(size_t)(qrow0 + r) * E3 + qoff + c]);
        }
    }
    CP_COMMIT;
    load_kv(0, 0); CP_COMMIT;
    CP_WAIT0;
    __syncthreads();

    // Hoist Q fragments (own 16 rows), pre-scaled by 1/sqrt(D)=0.125 (exact)
    uint32_t aq[8][4];
    {
        const float* Qtmp = Kraw + FK_WORDS;
#pragma unroll
        for (int ks = 0; ks < 8; ks++) {
            aq[ks][0] = __float_as_uint(Qtmp[(warp * 16 + lr) * FQ_STRIDE + ks * 8 + lc] * 0.125f);
            aq[ks][1] = __float_as_uint(Qtmp[(warp * 16 + lr + 8) * FQ_STRIDE + ks * 8 + lc] * 0.125f);
            aq[ks][2] = __float_as_uint(Qtmp[(warp * 16 + lr) * FQ_STRIDE + ks * 8 + lc + 4] * 0.125f);
            aq[ks][3] = __float_as_uint(Qtmp[(warp * 16 + lr + 8) * FQ_STRIDE + ks * 8 + lc + 4] * 0.125f);
        }
    }

    float o[8][4];
#pragma unroll
    for (int i = 0; i < 8; i++)
#pragma unroll
        for (int j = 0; j < 4; j++) o[i][j] = 0.f;
    float m0r = -1e30f, m1r = -1e30f, l0 = 0.f, l1 = 0.f;

    for (int kt = 0; kt <= qt; kt++) {
        const int s = kt & 1;
        CP_WAIT0;                        // stage-s K/V copies landed
        __syncthreads();                 // visible; all warps past stage s^1
                                         // (kt=0: separates aq reads from
                                         //  the overwrite of the Q buffer)
        if (kt < qt) load_kv(s ^ 1, kt + 1);
        CP_COMMIT;

        const float* Kf = Kraw + s * FK_WORDS;
        const float* Vf = Vraw + s * FV_WORDS;

        // S = Q @ K^T
        float sv[8][4];
#pragma unroll
        for (int i = 0; i < 8; i++)
#pragma unroll
            for (int j = 0; j < 4; j++) sv[i][j] = 0.f;

#pragma unroll
        for (int nt = 0; nt < 8; nt++) {
#pragma unroll
            for (int ks = 0; ks < 8; ks++) {
                uint32_t b0 = __float_as_uint(Kf[(nt * 8 + lr) * FQ_STRIDE + ks * 8 + lc]);
                uint32_t b1 = __float_as_uint(Kf[(nt * 8 + lr) * FQ_STRIDE + ks * 8 + lc + 4]);
                mma_tf32(sv[nt], aq[ks], b0, b1);
            }
        }

        // Causal mask (diagonal tile only)
        const int q0 = warp * 16 + lr, q1 = q0 + 8;
        if (kt == qt) {
#pragma unroll
            for (int nt = 0; nt < 8; nt++) {
                int c0 = nt * 8 + 2 * lc;
                if (c0     > q0) sv[nt][0] = -1e30f;
                if (c0 + 1 > q0) sv[nt][1] = -1e30f;
                if (c0     > q1) sv[nt][2] = -1e30f;
                if (c0 + 1 > q1) sv[nt][3] = -1e30f;
            }
        }

        // Online softmax
        float t0 = -1e30f, t1 = -1e30f;
#pragma unroll
        for (int nt = 0; nt < 8; nt++) {
            t0 = fmaxf(t0, fmaxf(sv[nt][0], sv[nt][1]));
            t1 = fmaxf(t1, fmaxf(sv[nt][2], sv[nt][3]));
        }
        t0 = fmaxf(t0, __shfl_xor_sync(0xffffffff, t0, 1));
        t0 = fmaxf(t0, __shfl_xor_sync(0xffffffff, t0, 2));
        t1 = fmaxf(t1, __shfl_xor_sync(0xffffffff, t1, 1));
        t1 = fmaxf(t1, __shfl_xor_sync(0xffffffff, t1, 2));

        float mn0 = fmaxf(m0r, t0), mn1 = fmaxf(m1r, t1);
        float al0 = __expf(m0r - mn0), al1 = __expf(m1r - mn1);
        m0r = mn0; m1r = mn1;

        float sum0 = 0.f, sum1 = 0.f;
#pragma unroll
        for (int nt = 0; nt < 8; nt++) {
            sv[nt][0] = __expf(sv[nt][0] - mn0);
            sv[nt][1] = __expf(sv[nt][1] - mn0);
            sv[nt][2] = __expf(sv[nt][2] - mn1);
            sv[nt][3] = __expf(sv[nt][3] - mn1);
            sum0 += sv[nt][0] + sv[nt][1];
            sum1 += sv[nt][2] + sv[nt][3];
        }
        sum0 += __shfl_xor_sync(0xffffffff, sum0, 1);
        sum0 += __shfl_xor_sync(0xffffffff, sum0, 2);
        sum1 += __shfl_xor_sync(0xffffffff, sum1, 1);
        sum1 += __shfl_xor_sync(0xffffffff, sum1, 2);
        l0 = l0 * al0 + sum0;
        l1 = l1 * al1 + sum1;

#pragma unroll
        for (int nt = 0; nt < 8; nt++) {
            o[nt][0] *= al0; o[nt][1] *= al0;
            o[nt][2] *= al1; o[nt][3] *= al1;
        }

        // O += P @ V, P a-frags built from S c-frags via intra-quad shuffles.
        // Value P(row, 8*ks + c) lives in reg (c&1 ? c1 : c0, +2 for row+8)
        // of lane 4*row + (c>>1). Target a-frag cols are lc and lc+4.
        const int lsrc = (lane & 28) | (lc >> 1);   // 4*lr + (lc>>1)
        const bool odd = (lc & 1);
#pragma unroll
        for (int ks = 0; ks < 8; ks++) {
            uint32_t p0 = f2tf(sv[ks][0]);
            uint32_t p1 = f2tf(sv[ks][1]);
            uint32_t p2 = f2tf(sv[ks][2]);
            uint32_t p3 = f2tf(sv[ks][3]);
            uint32_t q0v = __shfl_sync(0xffffffff, p0, lsrc);
            uint32_t q1v = __shfl_sync(0xffffffff, p1, lsrc);
            uint32_t q2v = __shfl_sync(0xffffffff, p2, lsrc);
            uint32_t q3v = __shfl_sync(0xffffffff, p3, lsrc);
            uint32_t u0v = __shfl_sync(0xffffffff, p0, lsrc + 2);
            uint32_t u1v = __shfl_sync(0xffffffff, p1, lsrc + 2);
            uint32_t u2v = __shfl_sync(0xffffffff, p2, lsrc + 2);
            uint32_t u3v = __shfl_sync(0xffffffff, p3, lsrc + 2);
            uint32_t ap[4];
            ap[0] = odd ? q1v : q0v;   // P(lr,   ks*8+lc)
            ap[1] = odd ? q3v : q2v;   // P(lr+8, ks*8+lc)
            ap[2] = odd ? u1v : u0v;   // P(lr,   ks*8+lc+4)
            ap[3] = odd ? u3v : u2v;   // P(lr+8, ks*8+lc+4)
#pragma unroll
            for (int nt = 0; nt < 8; nt++) {
                uint32_t b0 = __float_as_uint(Vf[(ks * 8 + lc) * FV_STRIDE + nt * 8 + lr]);
                uint32_t b1 = __float_as_uint(Vf[(ks * 8 + lc + 4) * FV_STRIDE + nt * 8 + lr]);
                mma_tf32(o[nt], ap, b0, b1);
            }
        }
    }

    // Epilogue: normalize, round to tf32 grid for proj GEMM, store
    const float inv0 = 1.f / l0, inv1 = 1.f / l1;
    const size_t row0 = (size_t)(b * TT + qrow0 + warp * 16 + lr) * EE + h * DD;
#pragma unroll
    for (int nt = 0; nt < 8; nt++) {
        int c = nt * 8 + 2 * lc;
        attn_out[row0 + c]              = __uint_as_float(f2tf(o[nt][0] * inv0));
        attn_out[row0 + c + 1]          = __uint_as_float(f2tf(o[nt][1] * inv0));
        attn_out[row0 + 8 * EE + c]     = __uint_as_float(f2tf(o[nt][2] * inv1));
        attn_out[row0 + 8 * EE + c + 1] = __uint_as_float(f2tf(o[nt][3] * inv1));
    }
}

// ---------------------------------------------------------------------------
extern "C" void kernel_launch(void* const* d_in, const int* in_sizes, int n_in,
                              void* d_out, int out_size)
{
    const float* x      = (const float*)d_in[0];
    const float* w_attn = (const float*)d_in[1];
    const float* b_attn = (const float*)d_in[2];
    const float* w_proj = (const float*)d_in[3];
    const float* b_proj = (const float*)d_in[4];
    float* out = (float*)d_out;

    float *qkv_ptr, *attn_ptr, *xtf, *watf, *wptf;
    cudaGetSymbolAddress((void**)&qkv_ptr, g_qkv);
    cudaGetSymbolAddress((void**)&attn_ptr, g_attn);
    cudaGetSymbolAddress((void**)&xtf,  g_x_tf);
    cudaGetSymbolAddress((void**)&watf, g_wa_tf);
    cudaGetSymbolAddress((void**)&wptf, g_wp_tf);

    cudaFuncSetAttribute(gemm_bias_kernel<18, 1>,
                         cudaFuncAttributeMaxDynamicSharedMemorySize, GEMM_SMEM);
    cudaFuncSetAttribute(gemm_bias_kernel<6, 0>,
                         cudaFuncAttributeMaxDynamicSharedMemorySize, GEMM_SMEM);
    cudaFuncSetAttribute(flash_attn_kernel,
                         cudaFuncAttributeMaxDynamicSharedMemorySize, FLASH_SMEM);

    // 0) pre-round inputs to the tf32 grid (single launch)
    cvt3_tf32_kernel<<<888, 256>>>(x, xtf, w_attn, watf, w_proj, wptf);

    // 1) QKV = x @ w_attn + b_attn [8192, 2304], persistent 444-CTA grid
    gemm_bias_kernel<18, 1><<<444, 128, GEMM_SMEM>>>(xtf, watf, b_attn, qkv_ptr);

    // 2) causal flash attention (Br=64, shuffle-P, 3 CTAs/SM) -> g_attn
    flash_attn_kernel<<<dim3(TT / 64, HH, BB), 128, FLASH_SMEM>>>(qkv_ptr, attn_ptr);

    // 3) out = attn @ w_proj + b_proj [8192, 768] (single wave)
    gemm_bias_kernel<6, 0><<<384, 128, GEMM_SMEM>>>(attn_ptr, wptf, b_proj, out);
}